// round 12
// baseline (speedup 1.0000x reference)
#include <cuda_runtime.h>
#include <cuda_fp16.h>
#include <cstdint>
#include <cstddef>

#define T_TOK 2048
#define H_DIM 2048
#define N_EXP 32
#define I_DIM 768
#define TOPK  8
#define PITCH 80        // smem row pitch bytes (32 halves + 16B skew)

// -------- static device scratch --------------------------------------------
__device__ int   g_cnt[N_EXP];
__device__ int   g_list[N_EXP * T_TOK];
__device__ float g_rw[T_TOK * TOPK];
__device__ __align__(16) __half g_xh[(size_t)T_TOK * H_DIM];          // 8 MB
__device__ __align__(16) __half g_wgh[(size_t)N_EXP * I_DIM * H_DIM]; // 96 MB
__device__ __align__(16) __half g_wuh[(size_t)N_EXP * I_DIM * H_DIM]; // 96 MB
__device__ __align__(16) __half g_wdh[(size_t)N_EXP * H_DIM * I_DIM]; // 96 MB
__device__ __align__(16) __half g_h[(size_t)T_TOK * TOPK * I_DIM];    // 25 MB

// -------- helpers -----------------------------------------------------------
__device__ __forceinline__ uint32_t sptr(const void* p) {
    return (uint32_t)__cvta_generic_to_shared(p);
}
__device__ __forceinline__ uint32_t pk2(float a, float b) {
    __half2 h = __floats2half2_rn(a, b);
    return *(uint32_t*)&h;
}
__device__ __forceinline__ void cp16(uint32_t dst, const void* src, int valid) {
    asm volatile("cp.async.cg.shared.global [%0], [%1], 16, %2;"
                 :: "r"(dst), "l"(src), "r"(valid ? 16 : 0));
}
#define CP_COMMIT() asm volatile("cp.async.commit_group;")
#define CP_WAIT1()  asm volatile("cp.async.wait_group 1;")
#define CP_WAIT0()  asm volatile("cp.async.wait_group 0;")

__device__ __forceinline__ void ldsm4(uint32_t* r, uint32_t a) {
    asm volatile("ldmatrix.sync.aligned.m8n8.x4.shared.b16 {%0,%1,%2,%3}, [%4];"
                 : "=r"(r[0]), "=r"(r[1]), "=r"(r[2]), "=r"(r[3]) : "r"(a));
}
__device__ __forceinline__ void mma16(float* d, const uint32_t* a,
                                      uint32_t b0, uint32_t b1) {
    asm volatile(
        "mma.sync.aligned.m16n8k16.row.col.f32.f16.f16.f32 "
        "{%0,%1,%2,%3},{%4,%5,%6,%7},{%8,%9},{%0,%1,%2,%3};"
        : "+f"(d[0]), "+f"(d[1]), "+f"(d[2]), "+f"(d[3])
        : "r"(a[0]), "r"(a[1]), "r"(a[2]), "r"(a[3]), "r"(b0), "r"(b1));
}

// -------- init: zero counters + output ----------------------------------------
__global__ __launch_bounds__(256) void init_kernel(float* __restrict__ out, int n)
{
    int i = blockIdx.x * 256 + threadIdx.x;
    if (i < N_EXP) g_cnt[i] = 0;
    for (int j = i; j < n; j += gridDim.x * 256) out[j] = 0.f;
}

// -------- fp32 -> fp16 streaming convert (8 elements / thread) ---------------
__global__ __launch_bounds__(256) void conv_kernel(
    const float* __restrict__ src, __half* __restrict__ dst)
{
    size_t i = (size_t)blockIdx.x * 256 + threadIdx.x;
    const float4* s = (const float4*)src + i * 2;
    float4 v0 = s[0], v1 = s[1];
    uint4 o;
    o.x = pk2(v0.x, v0.y); o.y = pk2(v0.z, v0.w);
    o.z = pk2(v1.x, v1.y); o.w = pk2(v1.z, v1.w);
    *(uint4*)&dst[i * 8] = o;
}

// -------- router ---------------------------------------------------------------
__global__ __launch_bounds__(256) void router_kernel(
    const float* __restrict__ x, const float* __restrict__ gw)
{
    __shared__ float xs[H_DIM];
    __shared__ float logits[N_EXP];

    const int t = blockIdx.x;
    const float* xr = x + (size_t)t * H_DIM;
    for (int i = threadIdx.x; i < H_DIM; i += 256) xs[i] = xr[i];
    __syncthreads();

    const int warp = threadIdx.x >> 5;
    const int lane = threadIdx.x & 31;

    float acc[4] = {0.f, 0.f, 0.f, 0.f};
    for (int k = lane; k < H_DIM; k += 32) {
        float xv = xs[k];
        #pragma unroll
        for (int q = 0; q < 4; q++)
            acc[q] = fmaf(xv, gw[(size_t)(warp * 4 + q) * H_DIM + k], acc[q]);
    }
    #pragma unroll
    for (int q = 0; q < 4; q++) {
        float v = acc[q];
        #pragma unroll
        for (int off = 16; off; off >>= 1)
            v += __shfl_down_sync(0xffffffffu, v, off);
        if (lane == 0) logits[warp * 4 + q] = v;
    }
    __syncthreads();

    if (threadIdx.x == 0) {
        float lg[N_EXP];
        #pragma unroll
        for (int i = 0; i < N_EXP; i++) lg[i] = logits[i];
        int   sel[TOPK];
        float sv[TOPK];
        #pragma unroll
        for (int s = 0; s < TOPK; s++) {
            int best = 0; float bv = -3.4e38f;
            #pragma unroll
            for (int i = 0; i < N_EXP; i++)
                if (lg[i] > bv) { bv = lg[i]; best = i; }
            sel[s] = best; sv[s] = bv; lg[best] = -3.4e38f;
        }
        float mx = sv[0];
        float ex[TOPK], sum = 0.f;
        #pragma unroll
        for (int s = 0; s < TOPK; s++) { ex[s] = __expf(sv[s] - mx); sum += ex[s]; }
        float inv = 1.f / sum;
        #pragma unroll
        for (int s = 0; s < TOPK; s++) {
            int e = sel[s];
            int pos = atomicAdd(&g_cnt[e], 1);
            g_list[e * T_TOK + pos] = t * TOPK + s;
            g_rw[t * TOPK + s] = ex[s] * inv;
        }
    }
}

// ============================================================================
// phase A: h = silu(x@Wg^T)*(x@Wu^T)*rw     fp16 MMA m16n8k16, fp32 accum
// BM=128, BN=64, BK=32; 8 warps 2M x 4N; warp tile 64x16 per tensor.
// All staged via cp.async from fp16 scratch; 3-stage pipeline (wait_group 1).
// stage = 20480 B; x3 = 61440 B
// ============================================================================
__global__ __launch_bounds__(256, 2) void phaseA_kernel()
{
    const int e    = blockIdx.z;
    const int cnt  = g_cnt[e];
    const int row0 = blockIdx.x * 128;
    if (row0 >= cnt) return;
    const int col0 = blockIdx.y * 64;

    extern __shared__ __align__(16) char dsm[];
    __shared__ int toks[128];

    const uint32_t S   = sptr(dsm);
    const uint32_t A0  = S;
    const uint32_t G0  = S + 10240;
    const uint32_t U0  = S + 15360;
    const uint32_t STG = 20480;

    const int tid = threadIdx.x;
    if (tid < 128) {
        int r = row0 + tid;
        toks[tid] = (r < cnt) ? g_list[e * T_TOK + r] : -1;
    }
    __syncthreads();

    const __half* wgE = g_wgh + (size_t)e * I_DIM * H_DIM + (size_t)col0 * H_DIM;
    const __half* wuE = g_wuh + (size_t)e * I_DIM * H_DIM + (size_t)col0 * H_DIM;

    const int warp = tid >> 5, lane = tid & 31;
    const int gid  = lane >> 2, tcol = lane & 3;
    const int mw0  = (warp & 1) * 64;
    const int nw0  = (warp >> 1) * 16;

    const uint32_t aoff = (uint32_t)(mw0 + (lane & 15)) * PITCH + ((lane >> 4) * 16);
    const uint32_t boff = (uint32_t)(nw0 + (lane & 15)) * PITCH + ((lane >> 4) * 16);

    float accG[4][2][4] = {};
    float accU[4][2][4] = {};

    const int ar0 = tid >> 2;            // 0..63
    const int sch = tid & 3;             // 16B chunk

    const int pk0 = toks[ar0], pk1 = toks[ar0 + 64];
    const __half* aS0 = (pk0 >= 0) ? &g_xh[(size_t)(pk0 >> 3) * H_DIM + sch * 8] : g_xh;
    const __half* aS1 = (pk1 >= 0) ? &g_xh[(size_t)(pk1 >> 3) * H_DIM + sch * 8] : g_xh;
    const __half* gS  = &wgE[(size_t)ar0 * H_DIM + sch * 8];
    const __half* uS  = &wuE[(size_t)ar0 * H_DIM + sch * 8];
    const uint32_t aD0 = A0 + ar0 * PITCH + sch * 16;
    const uint32_t aD1 = A0 + (ar0 + 64) * PITCH + sch * 16;
    const uint32_t gD  = G0 + ar0 * PITCH + sch * 16;
    const uint32_t uD  = U0 + ar0 * PITCH + sch * 16;

    auto stage = [&](int kt, int buf) {
        const int k0 = kt * 32;
        const uint32_t bo = buf * STG;
        cp16(aD0 + bo, aS0 + k0, pk0 >= 0);
        cp16(aD1 + bo, aS1 + k0, pk1 >= 0);
        cp16(gD + bo, gS + k0, 1);
        cp16(uD + bo, uS + k0, 1);
    };

    const int KT = H_DIM / 32;   // 64
    stage(0, 0); CP_COMMIT();
    stage(1, 1); CP_COMMIT();

    for (int kt = 0; kt < KT; kt++) {
        const int buf = kt % 3;
        if (kt + 1 < KT) { CP_WAIT1(); } else { CP_WAIT0(); }
        __syncthreads();
        if (kt + 2 < KT) { stage(kt + 2, (kt + 2) % 3); CP_COMMIT(); }

        const uint32_t Ab = A0 + buf * STG + aoff;
        const uint32_t Gb = G0 + buf * STG + boff;
        const uint32_t Ub = U0 + buf * STG + boff;

        #pragma unroll
        for (int kc = 0; kc < 2; kc++) {
            const uint32_t kb = kc * 32;
            uint32_t a[4][4];
            #pragma unroll
            for (int mf = 0; mf < 4; mf++) ldsm4(a[mf], Ab + mf * 16 * PITCH + kb);
            uint32_t bg[4], bu[4];
            ldsm4(bg, Gb + kb);
            ldsm4(bu, Ub + kb);
            #pragma unroll
            for (int mf = 0; mf < 4; mf++) {
                mma16(accG[mf][0], a[mf], bg[0], bg[2]);
                mma16(accG[mf][1], a[mf], bg[1], bg[3]);
                mma16(accU[mf][0], a[mf], bu[0], bu[2]);
                mma16(accU[mf][1], a[mf], bu[1], bu[3]);
            }
        }
    }

    // epilogue: silu(g)*u*rw -> g_h (fp16)
    #pragma unroll
    for (int mf = 0; mf < 4; mf++) {
        #pragma unroll
        for (int half = 0; half < 2; half++) {
            int rl = mw0 + mf * 16 + gid + half * 8;
            int pkk = toks[rl];
            if (pkk < 0) continue;
            float w = g_rw[pkk];
            #pragma unroll
            for (int nf = 0; nf < 2; nf++) {
                int c = col0 + nw0 + nf * 8 + 2 * tcol;
                float g0 = accG[mf][nf][half * 2 + 0];
                float g1 = accG[mf][nf][half * 2 + 1];
                float u0 = accU[mf][nf][half * 2 + 0];
                float u1 = accU[mf][nf][half * 2 + 1];
                float h0 = (g0 / (1.f + __expf(-g0))) * u0 * w;
                float h1 = (g1 / (1.f + __expf(-g1))) * u1 * w;
                *(uint32_t*)&g_h[(size_t)pkk * I_DIM + c] = pk2(h0, h1);
            }
        }
    }
}

// ============================================================================
// phase B: out[token] += h[pk] @ Wd^T    fp16 MMA, fp32 accum, atomic epilogue
// BM=128, BN=128, BK=32; 8 warps 2M x 4N; warp tile 64x32.
// 3-stage cp.async pipeline. stage = 20480 B; x3 = 61440 B
// ============================================================================
__global__ __launch_bounds__(256, 2) void phaseB_kernel(float* __restrict__ out)
{
    const int e    = blockIdx.z;
    const int cnt  = g_cnt[e];
    const int row0 = blockIdx.x * 128;
    if (row0 >= cnt) return;
    const int col0 = blockIdx.y * 128;

    extern __shared__ __align__(16) char dsm[];
    __shared__ int toks[128];

    const uint32_t S   = sptr(dsm);
    const uint32_t H0  = S;
    const uint32_t D0  = S + 10240;
    const uint32_t STG = 20480;

    const int tid = threadIdx.x;
    if (tid < 128) {
        int r = row0 + tid;
        toks[tid] = (r < cnt) ? g_list[e * T_TOK + r] : -1;
    }
    __syncthreads();

    const __half* wdE = g_wdh + (size_t)e * H_DIM * I_DIM + (size_t)col0 * I_DIM;

    const int warp = tid >> 5, lane = tid & 31;
    const int gid  = lane >> 2, tcol = lane & 3;
    const int mw0  = (warp & 1) * 64;
    const int nw0  = (warp >> 1) * 32;

    const uint32_t aoff = (uint32_t)(mw0 + (lane & 15)) * PITCH + ((lane >> 4) * 16);
    const uint32_t boff = (uint32_t)(nw0 + (lane & 15)) * PITCH + ((lane >> 4) * 16);

    float acc[4][4][4] = {};

    const int ar0 = tid >> 2;
    const int sch = tid & 3;

    const int pk0 = toks[ar0], pk1 = toks[ar0 + 64];
    const __half* hS0 = (pk0 >= 0) ? &g_h[(size_t)pk0 * I_DIM + sch * 8] : g_h;
    const __half* hS1 = (pk1 >= 0) ? &g_h[(size_t)pk1 * I_DIM + sch * 8] : g_h;
    const __half* dS0 = &wdE[(size_t)ar0 * I_DIM + sch * 8];
    const __half* dS1 = &wdE[(size_t)(ar0 + 64) * I_DIM + sch * 8];
    const uint32_t hD0 = H0 + ar0 * PITCH + sch * 16;
    const uint32_t hD1 = H0 + (ar0 + 64) * PITCH + sch * 16;
    const uint32_t dD0 = D0 + ar0 * PITCH + sch * 16;
    const uint32_t dD1 = D0 + (ar0 + 64) * PITCH + sch * 16;

    auto stage = [&](int kt, int buf) {
        const int k0 = kt * 32;
        const uint32_t bo = buf * STG;
        cp16(hD0 + bo, hS0 + k0, pk0 >= 0);
        cp16(hD1 + bo, hS1 + k0, pk1 >= 0);
        cp16(dD0 + bo, dS0 + k0, 1);
        cp16(dD1 + bo, dS1 + k0, 1);
    };

    const int KT = I_DIM / 32;   // 24
    stage(0, 0); CP_COMMIT();
    stage(1, 1); CP_COMMIT();

    for (int kt = 0; kt < KT; kt++) {
        const int buf = kt % 3;
        if (kt + 1 < KT) { CP_WAIT1(); } else { CP_WAIT0(); }
        __syncthreads();
        if (kt + 2 < KT) { stage(kt + 2, (kt + 2) % 3); CP_COMMIT(); }

        const uint32_t Hb = H0 + buf * STG + aoff;
        const uint32_t Db = D0 + buf * STG + boff;

        #pragma unroll
        for (int kc = 0; kc < 2; kc++) {
            const uint32_t kb = kc * 32;
            uint32_t a[4][4];
            #pragma unroll
            for (int mf = 0; mf < 4; mf++) ldsm4(a[mf], Hb + mf * 16 * PITCH + kb);
            uint32_t b[2][4];
            #pragma unroll
            for (int g = 0; g < 2; g++) ldsm4(b[g], Db + g * 16 * PITCH + kb);
            #pragma unroll
            for (int mf = 0; mf < 4; mf++)
                #pragma unroll
                for (int g = 0; g < 2; g++) {
                    mma16(acc[mf][g * 2 + 0], a[mf], b[g][0], b[g][2]);
                    mma16(acc[mf][g * 2 + 1], a[mf], b[g][1], b[g][3]);
                }
        }
    }

    // epilogue: atomic accumulate into out
    #pragma unroll
    for (int mf = 0; mf < 4; mf++) {
        #pragma unroll
        for (int half = 0; half < 2; half++) {
            int rl = mw0 + mf * 16 + gid + half * 8;
            int pkk = toks[rl];
            if (pkk < 0) continue;
            float* orow = out + (size_t)(pkk >> 3) * H_DIM;
            #pragma unroll
            for (int nf = 0; nf < 4; nf++) {
                int c = col0 + nw0 + nf * 8 + 2 * tcol;
                atomicAdd(&orow[c],     acc[mf][nf][half * 2 + 0]);
                atomicAdd(&orow[c + 1], acc[mf][nf][half * 2 + 1]);
            }
        }
    }
}

// ---------------------------------------------------------------------------
extern "C" void kernel_launch(void* const* d_in, const int* in_sizes, int n_in,
                              void* d_out, int out_size)
{
    const float* x  = (const float*)d_in[0];
    const float* gw = (const float*)d_in[1];
    const float* wg = (const float*)d_in[2];
    const float* wu = (const float*)d_in[3];
    const float* wd = (const float*)d_in[4];
    float* out = (float*)d_out;

    const int smemAB = 3 * 20480;   // 61440 B

    // one-time setup (first call is the non-captured correctness run)
    static cudaStream_t s2 = nullptr;
    static cudaEvent_t evRoot = nullptr, evGU = nullptr, evD = nullptr;
    if (!s2) {
        cudaFuncSetAttribute(phaseA_kernel, cudaFuncAttributeMaxDynamicSharedMemorySize, smemAB);
        cudaFuncSetAttribute(phaseB_kernel, cudaFuncAttributeMaxDynamicSharedMemorySize, smemAB);
        cudaStreamCreateWithFlags(&s2, cudaStreamNonBlocking);
        cudaEventCreateWithFlags(&evRoot, cudaEventDisableTiming);
        cudaEventCreateWithFlags(&evGU, cudaEventDisableTiming);
        cudaEventCreateWithFlags(&evD, cudaEventDisableTiming);
    }

    __half *xh_p, *wgh_p, *wuh_p, *wdh_p;
    cudaGetSymbolAddress((void**)&xh_p,  g_xh);
    cudaGetSymbolAddress((void**)&wgh_p, g_wgh);
    cudaGetSymbolAddress((void**)&wuh_p, g_wuh);
    cudaGetSymbolAddress((void**)&wdh_p, g_wdh);

    const int W_ELEM = N_EXP * I_DIM * H_DIM;          // 50331648

    // fork: weight conversions on s2, concurrent with init/x-conv/router
    cudaEventRecord(evRoot, 0);
    cudaStreamWaitEvent(s2, evRoot, 0);
    conv_kernel<<<(W_ELEM / 8) / 256, 256, 0, s2>>>(wg, wgh_p);
    conv_kernel<<<(W_ELEM / 8) / 256, 256, 0, s2>>>(wu, wuh_p);
    cudaEventRecord(evGU, s2);
    conv_kernel<<<(W_ELEM / 8) / 256, 256, 0, s2>>>(wd, wdh_p);
    cudaEventRecord(evD, s2);

    // main stream
    init_kernel<<<1024, 256>>>(out, out_size);
    conv_kernel<<<(T_TOK * H_DIM / 8) / 256, 256>>>(x, xh_p);
    router_kernel<<<T_TOK, 256>>>(x, gw);

    cudaStreamWaitEvent(0, evGU, 0);
    phaseA_kernel<<<dim3(16, I_DIM / 64, N_EXP), 256, smemAB>>>();
    cudaStreamWaitEvent(0, evD, 0);
    phaseB_kernel<<<dim3(16, H_DIM / 128, N_EXP), 256, smemAB>>>(out);
}

// round 13
// speedup vs baseline: 1.1066x; 1.1066x over previous
#include <cuda_runtime.h>
#include <cuda_fp16.h>
#include <cstdint>
#include <cstddef>

#define T_TOK 2048
#define H_DIM 2048
#define N_EXP 32
#define I_DIM 768
#define TOPK  8
#define PITCH 80        // smem row pitch bytes (32 halves + 16B skew)

// -------- static device scratch --------------------------------------------
__device__ int   g_cnt[N_EXP];
__device__ int   g_list[N_EXP * T_TOK];
__device__ float g_rw[T_TOK * TOPK];
__device__ __align__(16) __half g_xh[(size_t)T_TOK * H_DIM];        // 8 MB  x fp16
__device__ __align__(16) __half g_h[(size_t)T_TOK * TOPK * I_DIM];  // 25 MB h fp16

// -------- helpers -----------------------------------------------------------
__device__ __forceinline__ uint32_t sptr(const void* p) {
    return (uint32_t)__cvta_generic_to_shared(p);
}
__device__ __forceinline__ uint32_t pk2(float a, float b) {
    __half2 h = __floats2half2_rn(a, b);
    return *(uint32_t*)&h;
}
__device__ __forceinline__ void sts128(uint32_t a, uint32_t x0, uint32_t x1,
                                       uint32_t x2, uint32_t x3) {
    asm volatile("st.shared.v4.b32 [%0], {%1,%2,%3,%4};"
                 :: "r"(a), "r"(x0), "r"(x1), "r"(x2), "r"(x3));
}
__device__ __forceinline__ void cp16(uint32_t dst, const void* src, int valid) {
    asm volatile("cp.async.cg.shared.global [%0], [%1], 16, %2;"
                 :: "r"(dst), "l"(src), "r"(valid ? 16 : 0));
}
#define CP_COMMIT() asm volatile("cp.async.commit_group;")
#define CP_WAIT0()  asm volatile("cp.async.wait_group 0;")

__device__ __forceinline__ void ldsm4(uint32_t* r, uint32_t a) {
    asm volatile("ldmatrix.sync.aligned.m8n8.x4.shared.b16 {%0,%1,%2,%3}, [%4];"
                 : "=r"(r[0]), "=r"(r[1]), "=r"(r[2]), "=r"(r[3]) : "r"(a));
}
__device__ __forceinline__ void ldsm2(uint32_t* r, uint32_t a) {
    asm volatile("ldmatrix.sync.aligned.m8n8.x2.shared.b16 {%0,%1}, [%2];"
                 : "=r"(r[0]), "=r"(r[1]) : "r"(a));
}
__device__ __forceinline__ void mma16(float* d, const uint32_t* a,
                                      uint32_t b0, uint32_t b1) {
    asm volatile(
        "mma.sync.aligned.m16n8k16.row.col.f32.f16.f16.f32 "
        "{%0,%1,%2,%3},{%4,%5,%6,%7},{%8,%9},{%0,%1,%2,%3};"
        : "+f"(d[0]), "+f"(d[1]), "+f"(d[2]), "+f"(d[3])
        : "r"(a[0]), "r"(a[1]), "r"(a[2]), "r"(a[3]), "r"(b0), "r"(b1));
}

// -------- init: zero counters + output ----------------------------------------
__global__ __launch_bounds__(256) void init_kernel(float* __restrict__ out, int n)
{
    int i = blockIdx.x * 256 + threadIdx.x;
    if (i < N_EXP) g_cnt[i] = 0;
    for (int j = i; j < n; j += gridDim.x * 256) out[j] = 0.f;
}

// -------- router (also emits x in fp16 to g_xh) --------------------------------
__global__ __launch_bounds__(256) void router_kernel(
    const float* __restrict__ x, const float* __restrict__ gw)
{
    __shared__ float xs[H_DIM];
    __shared__ float logits[N_EXP];

    const int t = blockIdx.x;
    const float* xr = x + (size_t)t * H_DIM;
    for (int i = threadIdx.x; i < H_DIM; i += 256) xs[i] = xr[i];
    __syncthreads();

    // fused: write this token's row as fp16 (8 elements / thread)
    {
        const int b = threadIdx.x * 8;
        uint4 o;
        o.x = pk2(xs[b + 0], xs[b + 1]);
        o.y = pk2(xs[b + 2], xs[b + 3]);
        o.z = pk2(xs[b + 4], xs[b + 5]);
        o.w = pk2(xs[b + 6], xs[b + 7]);
        *(uint4*)&g_xh[(size_t)t * H_DIM + b] = o;
    }

    const int warp = threadIdx.x >> 5;
    const int lane = threadIdx.x & 31;

    float acc[4] = {0.f, 0.f, 0.f, 0.f};
    for (int k = lane; k < H_DIM; k += 32) {
        float xv = xs[k];
        #pragma unroll
        for (int q = 0; q < 4; q++)
            acc[q] = fmaf(xv, gw[(size_t)(warp * 4 + q) * H_DIM + k], acc[q]);
    }
    #pragma unroll
    for (int q = 0; q < 4; q++) {
        float v = acc[q];
        #pragma unroll
        for (int off = 16; off; off >>= 1)
            v += __shfl_down_sync(0xffffffffu, v, off);
        if (lane == 0) logits[warp * 4 + q] = v;
    }
    __syncthreads();

    if (threadIdx.x == 0) {
        float lg[N_EXP];
        #pragma unroll
        for (int i = 0; i < N_EXP; i++) lg[i] = logits[i];
        int   sel[TOPK];
        float sv[TOPK];
        #pragma unroll
        for (int s = 0; s < TOPK; s++) {
            int best = 0; float bv = -3.4e38f;
            #pragma unroll
            for (int i = 0; i < N_EXP; i++)
                if (lg[i] > bv) { bv = lg[i]; best = i; }
            sel[s] = best; sv[s] = bv; lg[best] = -3.4e38f;
        }
        float mx = sv[0];
        float ex[TOPK], sum = 0.f;
        #pragma unroll
        for (int s = 0; s < TOPK; s++) { ex[s] = __expf(sv[s] - mx); sum += ex[s]; }
        float inv = 1.f / sum;
        #pragma unroll
        for (int s = 0; s < TOPK; s++) {
            int e = sel[s];
            int pos = atomicAdd(&g_cnt[e], 1);
            g_list[e * T_TOK + pos] = t * TOPK + s;
            g_rw[t * TOPK + s] = ex[s] * inv;
        }
    }
}

// ============================================================================
// phase A: h = silu(x@Wg^T)*(x@Wu^T)*rw     fp16 MMA m16n8k16, fp32 accum
// BM=128, BN=64, BK=32; 8 warps 2M x 4N; warp tile 64x16 per tensor.
// A via cp.async(g_xh); Wg/Wu via LDG->cvt.f16x2->STS.128 reg pipeline.
// stage = A 10240 + G 5120 + U 5120 = 20480 B; x2 = 40960 B
// ============================================================================
__global__ __launch_bounds__(256, 2) void phaseA_kernel(
    const float* __restrict__ wg, const float* __restrict__ wu)
{
    const int e    = blockIdx.z;
    const int cnt  = g_cnt[e];
    const int row0 = blockIdx.x * 128;
    if (row0 >= cnt) return;
    const int col0 = blockIdx.y * 64;

    extern __shared__ __align__(16) char dsm[];
    __shared__ int toks[128];

    const uint32_t S   = sptr(dsm);
    const uint32_t A0  = S;
    const uint32_t G0  = S + 10240;
    const uint32_t U0  = S + 15360;
    const uint32_t STG = 20480;

    const int tid = threadIdx.x;
    if (tid < 128) {
        int r = row0 + tid;
        toks[tid] = (r < cnt) ? g_list[e * T_TOK + r] : -1;
    }
    __syncthreads();

    const float* wgE = wg + (size_t)e * I_DIM * H_DIM + (size_t)col0 * H_DIM;
    const float* wuE = wu + (size_t)e * I_DIM * H_DIM + (size_t)col0 * H_DIM;

    const int warp = tid >> 5, lane = tid & 31;
    const int gid  = lane >> 2, tcol = lane & 3;
    const int mw0  = (warp & 1) * 64;
    const int nw0  = (warp >> 1) * 16;

    const uint32_t aoff = (uint32_t)(mw0 + (lane & 15)) * PITCH + ((lane >> 4) * 16);
    const uint32_t boff = (uint32_t)(nw0 + (lane & 7)) * PITCH + (((lane >> 3) & 1) * 16);

    float accG[4][2][4] = {};
    float accU[4][2][4] = {};
    float4 gq[2], uq[2];

    const int wr = tid >> 2;        // weight row 0..63
    const int wc = tid & 3;         // 16B chunk 0..3

    auto ldgA = [&](int kt, int buf) {
        const int k0 = kt * 32;
        #pragma unroll
        for (int j = 0; j < 2; j++) {
            int idx = j * 256 + tid;          // 512 chunks
            int r   = idx >> 2;
            int ch  = idx & 3;
            int pkk = toks[r];
            const __half* src = (pkk >= 0)
                ? &g_xh[(size_t)(pkk >> 3) * H_DIM + k0 + ch * 8] : g_xh;
            cp16(A0 + buf * STG + r * PITCH + ch * 16, src, pkk >= 0);
        }
    };
    auto ldgW = [&](int kt) {
        const int k0 = kt * 32;
        const float* sg = &wgE[(size_t)wr * H_DIM + k0 + wc * 8];
        const float* su = &wuE[(size_t)wr * H_DIM + k0 + wc * 8];
        gq[0] = *(const float4*)sg; gq[1] = *(const float4*)(sg + 4);
        uq[0] = *(const float4*)su; uq[1] = *(const float4*)(su + 4);
    };
    auto stsW = [&](int buf) {
        uint32_t a = G0 + buf * STG + wr * PITCH + wc * 16;
        sts128(a, pk2(gq[0].x, gq[0].y), pk2(gq[0].z, gq[0].w),
                  pk2(gq[1].x, gq[1].y), pk2(gq[1].z, gq[1].w));
        uint32_t b = U0 + buf * STG + wr * PITCH + wc * 16;
        sts128(b, pk2(uq[0].x, uq[0].y), pk2(uq[0].z, uq[0].w),
                  pk2(uq[1].x, uq[1].y), pk2(uq[1].z, uq[1].w));
    };

    const int KT = H_DIM / 32;   // 64
    ldgA(0, 0); CP_COMMIT();
    ldgW(0);

    for (int kt = 0; kt < KT; kt++) {
        const int buf = kt & 1;
        stsW(buf);
        CP_WAIT0();
        __syncthreads();
        if (kt + 1 < KT) {
            ldgA(kt + 1, buf ^ 1); CP_COMMIT();
            ldgW(kt + 1);
        }

        const uint32_t Ab = A0 + buf * STG + aoff;
        const uint32_t Gb = G0 + buf * STG + boff;
        const uint32_t Ub = U0 + buf * STG + boff;

        #pragma unroll
        for (int kc = 0; kc < 2; kc++) {
            const uint32_t kb = kc * 32;
            uint32_t a[4][4];
            #pragma unroll
            for (int mf = 0; mf < 4; mf++) ldsm4(a[mf], Ab + mf * 16 * PITCH + kb);
            uint32_t bg[2][2], bu[2][2];
            #pragma unroll
            for (int nf = 0; nf < 2; nf++) {
                ldsm2(bg[nf], Gb + nf * 8 * PITCH + kb);
                ldsm2(bu[nf], Ub + nf * 8 * PITCH + kb);
            }
            #pragma unroll
            for (int mf = 0; mf < 4; mf++)
                #pragma unroll
                for (int nf = 0; nf < 2; nf++) {
                    mma16(accG[mf][nf], a[mf], bg[nf][0], bg[nf][1]);
                    mma16(accU[mf][nf], a[mf], bu[nf][0], bu[nf][1]);
                }
        }
    }

    // epilogue: silu(g)*u*rw -> g_h (fp16)
    #pragma unroll
    for (int mf = 0; mf < 4; mf++) {
        #pragma unroll
        for (int half = 0; half < 2; half++) {
            int rl = mw0 + mf * 16 + gid + half * 8;
            int pkk = toks[rl];
            if (pkk < 0) continue;
            float w = g_rw[pkk];
            #pragma unroll
            for (int nf = 0; nf < 2; nf++) {
                int c = col0 + nw0 + nf * 8 + 2 * tcol;
                float g0 = accG[mf][nf][half * 2 + 0];
                float g1 = accG[mf][nf][half * 2 + 1];
                float u0 = accU[mf][nf][half * 2 + 0];
                float u1 = accU[mf][nf][half * 2 + 1];
                float h0 = (g0 / (1.f + __expf(-g0))) * u0 * w;
                float h1 = (g1 / (1.f + __expf(-g1))) * u1 * w;
                *(uint32_t*)&g_h[(size_t)pkk * I_DIM + c] = pk2(h0, h1);
            }
        }
    }
}

// ============================================================================
// phase B: out[token] += h[pk] @ Wd^T   fp16 MMA, fp32 accum, atomic epilogue
// BM=128, BN=128, BK=32; 8 warps 2M x 4N; warp tile 64x32.
// stage = H 10240 + D 10240 = 20480 B; x2 = 40960 B
// ============================================================================
__global__ __launch_bounds__(256, 2) void phaseB_kernel(
    const float* __restrict__ wd, float* __restrict__ out)
{
    const int e    = blockIdx.z;
    const int cnt  = g_cnt[e];
    const int row0 = blockIdx.x * 128;
    if (row0 >= cnt) return;
    const int col0 = blockIdx.y * 128;

    extern __shared__ __align__(16) char dsm[];
    __shared__ int toks[128];

    const uint32_t S   = sptr(dsm);
    const uint32_t H0  = S;
    const uint32_t D0  = S + 10240;
    const uint32_t STG = 20480;

    const int tid = threadIdx.x;
    if (tid < 128) {
        int r = row0 + tid;
        toks[tid] = (r < cnt) ? g_list[e * T_TOK + r] : -1;
    }
    __syncthreads();

    const float* wdE = wd + (size_t)e * H_DIM * I_DIM + (size_t)col0 * I_DIM;

    const int warp = tid >> 5, lane = tid & 31;
    const int gid  = lane >> 2, tcol = lane & 3;
    const int mw0  = (warp & 1) * 64;
    const int nw0  = (warp >> 1) * 32;

    const uint32_t aoff = (uint32_t)(mw0 + (lane & 15)) * PITCH + ((lane >> 4) * 16);
    const uint32_t boff = (uint32_t)(nw0 + (lane & 15)) * PITCH + ((lane >> 4) * 16);

    float acc[4][4][4] = {};
    float4 dq[4];

    auto ldgH = [&](int kt, int buf) {
        const int k0 = kt * 32;
        #pragma unroll
        for (int j = 0; j < 2; j++) {
            int idx = j * 256 + tid;
            int r   = idx >> 2;
            int ch  = idx & 3;
            int pkk = toks[r];
            const __half* src = (pkk >= 0)
                ? &g_h[(size_t)pkk * I_DIM + k0 + ch * 8] : g_h;
            cp16(H0 + buf * STG + r * PITCH + ch * 16, src, pkk >= 0);
        }
    };
    auto ldgW = [&](int kt) {
        const int k0 = kt * 32;
        #pragma unroll
        for (int j = 0; j < 2; j++) {
            int idx = j * 256 + tid;
            int r   = idx >> 2;
            int ch  = idx & 3;
            const float* s = &wdE[(size_t)r * I_DIM + k0 + ch * 8];
            dq[j * 2]     = *(const float4*)s;
            dq[j * 2 + 1] = *(const float4*)(s + 4);
        }
    };
    auto stsW = [&](int buf) {
        #pragma unroll
        for (int j = 0; j < 2; j++) {
            int idx = j * 256 + tid;
            int r   = idx >> 2;
            int ch  = idx & 3;
            uint32_t a = D0 + buf * STG + r * PITCH + ch * 16;
            sts128(a, pk2(dq[j*2].x, dq[j*2].y), pk2(dq[j*2].z, dq[j*2].w),
                      pk2(dq[j*2+1].x, dq[j*2+1].y), pk2(dq[j*2+1].z, dq[j*2+1].w));
        }
    };

    const int KT = I_DIM / 32;   // 24
    ldgH(0, 0); CP_COMMIT();
    ldgW(0);

    for (int kt = 0; kt < KT; kt++) {
        const int buf = kt & 1;
        stsW(buf);
        CP_WAIT0();
        __syncthreads();
        if (kt + 1 < KT) {
            ldgH(kt + 1, buf ^ 1); CP_COMMIT();
            ldgW(kt + 1);
        }

        const uint32_t Hb = H0 + buf * STG + aoff;
        const uint32_t Db = D0 + buf * STG + boff;

        #pragma unroll
        for (int kc = 0; kc < 2; kc++) {
            const uint32_t kb = kc * 32;
            uint32_t a[4][4];
            #pragma unroll
            for (int mf = 0; mf < 4; mf++) ldsm4(a[mf], Hb + mf * 16 * PITCH + kb);
            uint32_t b[2][4];
            #pragma unroll
            for (int g = 0; g < 2; g++) ldsm4(b[g], Db + g * 16 * PITCH + kb);
            #pragma unroll
            for (int mf = 0; mf < 4; mf++)
                #pragma unroll
                for (int g = 0; g < 2; g++) {
                    mma16(acc[mf][g * 2 + 0], a[mf], b[g][0], b[g][2]);
                    mma16(acc[mf][g * 2 + 1], a[mf], b[g][1], b[g][3]);
                }
        }
    }

    // epilogue: atomic accumulate into out
    #pragma unroll
    for (int mf = 0; mf < 4; mf++) {
        #pragma unroll
        for (int half = 0; half < 2; half++) {
            int rl = mw0 + mf * 16 + gid + half * 8;
            int pkk = toks[rl];
            if (pkk < 0) continue;
            float* orow = out + (size_t)(pkk >> 3) * H_DIM;
            #pragma unroll
            for (int nf = 0; nf < 4; nf++) {
                int c = col0 + nw0 + nf * 8 + 2 * tcol;
                atomicAdd(&orow[c],     acc[mf][nf][half * 2 + 0]);
                atomicAdd(&orow[c + 1], acc[mf][nf][half * 2 + 1]);
            }
        }
    }
}

// ---------------------------------------------------------------------------
extern "C" void kernel_launch(void* const* d_in, const int* in_sizes, int n_in,
                              void* d_out, int out_size)
{
    const float* x  = (const float*)d_in[0];
    const float* gw = (const float*)d_in[1];
    const float* wg = (const float*)d_in[2];
    const float* wu = (const float*)d_in[3];
    const float* wd = (const float*)d_in[4];
    float* out = (float*)d_out;

    const int smemAB = 2 * 20480;   // 40960 B
    static bool attr_done = false;
    if (!attr_done) {
        cudaFuncSetAttribute(phaseA_kernel, cudaFuncAttributeMaxDynamicSharedMemorySize, smemAB);
        cudaFuncSetAttribute(phaseB_kernel, cudaFuncAttributeMaxDynamicSharedMemorySize, smemAB);
        attr_done = true;
    }

    init_kernel<<<1024, 256>>>(out, out_size);
    router_kernel<<<T_TOK, 256>>>(x, gw);
    phaseA_kernel<<<dim3(16, I_DIM / 64, N_EXP), 256, smemAB>>>(wg, wu);
    phaseB_kernel<<<dim3(16, H_DIM / 128, N_EXP), 256, smemAB>>>(wd, out);
}

// round 14
// speedup vs baseline: 1.1085x; 1.0017x over previous
#include <cuda_runtime.h>
#include <cuda_fp16.h>
#include <cstdint>
#include <cstddef>

#define T_TOK 2048
#define H_DIM 2048
#define N_EXP 32
#define I_DIM 768
#define TOPK  8
#define PITCH 80        // smem row pitch bytes (32 halves + 16B skew)

// -------- static device scratch --------------------------------------------
__device__ int   g_cnt[N_EXP];
__device__ int   g_list[N_EXP * T_TOK];
__device__ float g_rw[T_TOK * TOPK];
__device__ __align__(16) __half g_xh[(size_t)T_TOK * H_DIM];        // 8 MB  x fp16
__device__ __align__(16) __half g_h[(size_t)T_TOK * TOPK * I_DIM];  // 25 MB h fp16

// -------- helpers -----------------------------------------------------------
__device__ __forceinline__ uint32_t sptr(const void* p) {
    return (uint32_t)__cvta_generic_to_shared(p);
}
__device__ __forceinline__ uint32_t pk2(float a, float b) {
    __half2 h = __floats2half2_rn(a, b);
    return *(uint32_t*)&h;
}
__device__ __forceinline__ void sts128(uint32_t a, uint32_t x0, uint32_t x1,
                                       uint32_t x2, uint32_t x3) {
    asm volatile("st.shared.v4.b32 [%0], {%1,%2,%3,%4};"
                 :: "r"(a), "r"(x0), "r"(x1), "r"(x2), "r"(x3));
}
__device__ __forceinline__ void cp16(uint32_t dst, const void* src, int valid) {
    asm volatile("cp.async.cg.shared.global [%0], [%1], 16, %2;"
                 :: "r"(dst), "l"(src), "r"(valid ? 16 : 0));
}
#define CP_COMMIT() asm volatile("cp.async.commit_group;")
#define CP_WAIT0()  asm volatile("cp.async.wait_group 0;")

__device__ __forceinline__ void ldsm4(uint32_t* r, uint32_t a) {
    asm volatile("ldmatrix.sync.aligned.m8n8.x4.shared.b16 {%0,%1,%2,%3}, [%4];"
                 : "=r"(r[0]), "=r"(r[1]), "=r"(r[2]), "=r"(r[3]) : "r"(a));
}
__device__ __forceinline__ void mma16(float* d, const uint32_t* a,
                                      uint32_t b0, uint32_t b1) {
    asm volatile(
        "mma.sync.aligned.m16n8k16.row.col.f32.f16.f16.f32 "
        "{%0,%1,%2,%3},{%4,%5,%6,%7},{%8,%9},{%0,%1,%2,%3};"
        : "+f"(d[0]), "+f"(d[1]), "+f"(d[2]), "+f"(d[3])
        : "r"(a[0]), "r"(a[1]), "r"(a[2]), "r"(a[3]), "r"(b0), "r"(b1));
}

// -------- init: zero counters + output ----------------------------------------
__global__ __launch_bounds__(256) void init_kernel(float* __restrict__ out, int n)
{
    int i = blockIdx.x * 256 + threadIdx.x;
    if (i < N_EXP) g_cnt[i] = 0;
    for (int j = i; j < n; j += gridDim.x * 256) out[j] = 0.f;
}

// -------- router (also emits x in fp16 to g_xh) --------------------------------
__global__ __launch_bounds__(256) void router_kernel(
    const float* __restrict__ x, const float* __restrict__ gw)
{
    __shared__ float xs[H_DIM];
    __shared__ float logits[N_EXP];

    const int t = blockIdx.x;
    const float* xr = x + (size_t)t * H_DIM;
    for (int i = threadIdx.x; i < H_DIM; i += 256) xs[i] = xr[i];
    __syncthreads();

    // fused: write this token's row as fp16 (8 elements / thread)
    {
        const int b = threadIdx.x * 8;
        uint4 o;
        o.x = pk2(xs[b + 0], xs[b + 1]);
        o.y = pk2(xs[b + 2], xs[b + 3]);
        o.z = pk2(xs[b + 4], xs[b + 5]);
        o.w = pk2(xs[b + 6], xs[b + 7]);
        *(uint4*)&g_xh[(size_t)t * H_DIM + b] = o;
    }

    const int warp = threadIdx.x >> 5;
    const int lane = threadIdx.x & 31;

    float acc[4] = {0.f, 0.f, 0.f, 0.f};
    for (int k = lane; k < H_DIM; k += 32) {
        float xv = xs[k];
        #pragma unroll
        for (int q = 0; q < 4; q++)
            acc[q] = fmaf(xv, gw[(size_t)(warp * 4 + q) * H_DIM + k], acc[q]);
    }
    #pragma unroll
    for (int q = 0; q < 4; q++) {
        float v = acc[q];
        #pragma unroll
        for (int off = 16; off; off >>= 1)
            v += __shfl_down_sync(0xffffffffu, v, off);
        if (lane == 0) logits[warp * 4 + q] = v;
    }
    __syncthreads();

    if (threadIdx.x == 0) {
        float lg[N_EXP];
        #pragma unroll
        for (int i = 0; i < N_EXP; i++) lg[i] = logits[i];
        int   sel[TOPK];
        float sv[TOPK];
        #pragma unroll
        for (int s = 0; s < TOPK; s++) {
            int best = 0; float bv = -3.4e38f;
            #pragma unroll
            for (int i = 0; i < N_EXP; i++)
                if (lg[i] > bv) { bv = lg[i]; best = i; }
            sel[s] = best; sv[s] = bv; lg[best] = -3.4e38f;
        }
        float mx = sv[0];
        float ex[TOPK], sum = 0.f;
        #pragma unroll
        for (int s = 0; s < TOPK; s++) { ex[s] = __expf(sv[s] - mx); sum += ex[s]; }
        float inv = 1.f / sum;
        #pragma unroll
        for (int s = 0; s < TOPK; s++) {
            int e = sel[s];
            int pos = atomicAdd(&g_cnt[e], 1);
            g_list[e * T_TOK + pos] = t * TOPK + s;
            g_rw[t * TOPK + s] = ex[s] * inv;
        }
    }
}

// ============================================================================
// phase A: h = silu(x@Wg^T)*(x@Wu^T)*rw     fp16 MMA m16n8k16, fp32 accum
// BM=128, BN=64, BK=32; 8 warps 2M x 4N; warp tile 64x16 per tensor.
// B fragments via merged ldsm4 (both n8-groups in one instruction).
// Manual kt unroll x2 (buf compile-time const per body).
// ============================================================================
__global__ __launch_bounds__(256, 2) void phaseA_kernel(
    const float* __restrict__ wg, const float* __restrict__ wu)
{
    const int e    = blockIdx.z;
    const int cnt  = g_cnt[e];
    const int row0 = blockIdx.x * 128;
    if (row0 >= cnt) return;
    const int col0 = blockIdx.y * 64;

    extern __shared__ __align__(16) char dsm[];
    __shared__ int toks[128];

    const uint32_t S   = sptr(dsm);
    const uint32_t A0  = S;
    const uint32_t G0  = S + 10240;
    const uint32_t U0  = S + 15360;
    const uint32_t STG = 20480;

    const int tid = threadIdx.x;
    if (tid < 128) {
        int r = row0 + tid;
        toks[tid] = (r < cnt) ? g_list[e * T_TOK + r] : -1;
    }
    __syncthreads();

    const float* wgE = wg + (size_t)e * I_DIM * H_DIM + (size_t)col0 * H_DIM;
    const float* wuE = wu + (size_t)e * I_DIM * H_DIM + (size_t)col0 * H_DIM;

    const int warp = tid >> 5, lane = tid & 31;
    const int gid  = lane >> 2, tcol = lane & 3;
    const int mw0  = (warp & 1) * 64;
    const int nw0  = (warp >> 1) * 16;

    const uint32_t aoff = (uint32_t)(mw0 + (lane & 15)) * PITCH + ((lane >> 4) * 16);
    // merged-B ldsm4 mapping: lanes 0-7: n0-7/k0-7, 8-15: n0-7/k8-15,
    //                         16-23: n8-15/k0-7, 24-31: n8-15/k8-15
    const uint32_t boff = (uint32_t)(nw0 + ((lane >> 4) << 3) + (lane & 7)) * PITCH
                        + (((lane >> 3) & 1) * 16);

    float accG[4][2][4] = {};
    float accU[4][2][4] = {};
    float4 gq[2], uq[2];

    const int wr = tid >> 2;        // weight row 0..63
    const int wc = tid & 3;         // 16B chunk 0..3

    auto ldgA = [&](int kt, int buf) {
        const int k0 = kt * 32;
        #pragma unroll
        for (int j = 0; j < 2; j++) {
            int idx = j * 256 + tid;          // 512 chunks
            int r   = idx >> 2;
            int ch  = idx & 3;
            int pkk = toks[r];
            const __half* src = (pkk >= 0)
                ? &g_xh[(size_t)(pkk >> 3) * H_DIM + k0 + ch * 8] : g_xh;
            cp16(A0 + buf * STG + r * PITCH + ch * 16, src, pkk >= 0);
        }
    };
    auto ldgW = [&](int kt) {
        const int k0 = kt * 32;
        const float* sg = &wgE[(size_t)wr * H_DIM + k0 + wc * 8];
        const float* su = &wuE[(size_t)wr * H_DIM + k0 + wc * 8];
        gq[0] = *(const float4*)sg; gq[1] = *(const float4*)(sg + 4);
        uq[0] = *(const float4*)su; uq[1] = *(const float4*)(su + 4);
    };
    auto stsW = [&](int buf) {
        uint32_t a = G0 + buf * STG + wr * PITCH + wc * 16;
        sts128(a, pk2(gq[0].x, gq[0].y), pk2(gq[0].z, gq[0].w),
                  pk2(gq[1].x, gq[1].y), pk2(gq[1].z, gq[1].w));
        uint32_t b = U0 + buf * STG + wr * PITCH + wc * 16;
        sts128(b, pk2(uq[0].x, uq[0].y), pk2(uq[0].z, uq[0].w),
                  pk2(uq[1].x, uq[1].y), pk2(uq[1].z, uq[1].w));
    };
    auto compute = [&](int buf) {
        const uint32_t Ab = A0 + buf * STG + aoff;
        const uint32_t Gb = G0 + buf * STG + boff;
        const uint32_t Ub = U0 + buf * STG + boff;
        #pragma unroll
        for (int kc = 0; kc < 2; kc++) {
            const uint32_t kb = kc * 32;
            uint32_t a[4][4];
            #pragma unroll
            for (int mf = 0; mf < 4; mf++) ldsm4(a[mf], Ab + mf * 16 * PITCH + kb);
            uint32_t bg[4], bu[4];
            ldsm4(bg, Gb + kb);
            ldsm4(bu, Ub + kb);
            #pragma unroll
            for (int mf = 0; mf < 4; mf++) {
                mma16(accG[mf][0], a[mf], bg[0], bg[1]);
                mma16(accG[mf][1], a[mf], bg[2], bg[3]);
                mma16(accU[mf][0], a[mf], bu[0], bu[1]);
                mma16(accU[mf][1], a[mf], bu[2], bu[3]);
            }
        }
    };

    const int KT = H_DIM / 32;   // 64 (even)
    ldgA(0, 0); CP_COMMIT();
    ldgW(0);

    for (int kt = 0; kt < KT; kt += 2) {
        // ---- body 0 (buf 0) ----
        stsW(0);
        CP_WAIT0();
        __syncthreads();
        ldgA(kt + 1, 1); CP_COMMIT();
        ldgW(kt + 1);
        compute(0);
        // ---- body 1 (buf 1) ----
        stsW(1);
        CP_WAIT0();
        __syncthreads();
        if (kt + 2 < KT) {
            ldgA(kt + 2, 0); CP_COMMIT();
            ldgW(kt + 2);
        }
        compute(1);
    }

    // epilogue: silu(g)*u*rw -> g_h (fp16)
    #pragma unroll
    for (int mf = 0; mf < 4; mf++) {
        #pragma unroll
        for (int half = 0; half < 2; half++) {
            int rl = mw0 + mf * 16 + gid + half * 8;
            int pkk = toks[rl];
            if (pkk < 0) continue;
            float w = g_rw[pkk];
            #pragma unroll
            for (int nf = 0; nf < 2; nf++) {
                int c = col0 + nw0 + nf * 8 + 2 * tcol;
                float g0 = accG[mf][nf][half * 2 + 0];
                float g1 = accG[mf][nf][half * 2 + 1];
                float u0 = accU[mf][nf][half * 2 + 0];
                float u1 = accU[mf][nf][half * 2 + 1];
                float h0 = (g0 / (1.f + __expf(-g0))) * u0 * w;
                float h1 = (g1 / (1.f + __expf(-g1))) * u1 * w;
                *(uint32_t*)&g_h[(size_t)pkk * I_DIM + c] = pk2(h0, h1);
            }
        }
    }
}

// ============================================================================
// phase B: out[token] += h[pk] @ Wd^T   fp16 MMA, fp32 accum, atomic epilogue
// BM=128, BN=128, BK=32; 8 warps 2M x 4N; warp tile 64x32.
// Manual kt unroll x2.
// ============================================================================
__global__ __launch_bounds__(256, 2) void phaseB_kernel(
    const float* __restrict__ wd, float* __restrict__ out)
{
    const int e    = blockIdx.z;
    const int cnt  = g_cnt[e];
    const int row0 = blockIdx.x * 128;
    if (row0 >= cnt) return;
    const int col0 = blockIdx.y * 128;

    extern __shared__ __align__(16) char dsm[];
    __shared__ int toks[128];

    const uint32_t S   = sptr(dsm);
    const uint32_t H0  = S;
    const uint32_t D0  = S + 10240;
    const uint32_t STG = 20480;

    const int tid = threadIdx.x;
    if (tid < 128) {
        int r = row0 + tid;
        toks[tid] = (r < cnt) ? g_list[e * T_TOK + r] : -1;
    }
    __syncthreads();

    const float* wdE = wd + (size_t)e * H_DIM * I_DIM + (size_t)col0 * I_DIM;

    const int warp = tid >> 5, lane = tid & 31;
    const int gid  = lane >> 2, tcol = lane & 3;
    const int mw0  = (warp & 1) * 64;
    const int nw0  = (warp >> 1) * 32;

    const uint32_t aoff = (uint32_t)(mw0 + (lane & 15)) * PITCH + ((lane >> 4) * 16);
    const uint32_t boff = (uint32_t)(nw0 + (lane & 15)) * PITCH + ((lane >> 4) * 16);

    float acc[4][4][4] = {};
    float4 dq[4];

    const int ar0 = tid >> 2;
    const int sch = tid & 3;

    auto ldgH = [&](int kt, int buf) {
        const int k0 = kt * 32;
        #pragma unroll
        for (int j = 0; j < 2; j++) {
            int idx = j * 256 + tid;
            int r   = idx >> 2;
            int ch  = idx & 3;
            int pkk = toks[r];
            const __half* src = (pkk >= 0)
                ? &g_h[(size_t)pkk * I_DIM + k0 + ch * 8] : g_h;
            cp16(H0 + buf * STG + r * PITCH + ch * 16, src, pkk >= 0);
        }
    };
    auto ldgW = [&](int kt) {
        const int k0 = kt * 32;
        #pragma unroll
        for (int j = 0; j < 2; j++) {
            int idx = j * 256 + tid;
            int r   = idx >> 2;
            int ch  = idx & 3;
            const float* s = &wdE[(size_t)r * I_DIM + k0 + ch * 8];
            dq[j * 2]     = *(const float4*)s;
            dq[j * 2 + 1] = *(const float4*)(s + 4);
        }
    };
    auto stsW = [&](int buf) {
        #pragma unroll
        for (int j = 0; j < 2; j++) {
            int idx = j * 256 + tid;
            int r   = idx >> 2;
            int ch  = idx & 3;
            uint32_t a = D0 + buf * STG + r * PITCH + ch * 16;
            sts128(a, pk2(dq[j*2].x, dq[j*2].y), pk2(dq[j*2].z, dq[j*2].w),
                      pk2(dq[j*2+1].x, dq[j*2+1].y), pk2(dq[j*2+1].z, dq[j*2+1].w));
        }
    };
    auto compute = [&](int buf) {
        const uint32_t Hb = H0 + buf * STG + aoff;
        const uint32_t Db = D0 + buf * STG + boff;
        #pragma unroll
        for (int kc = 0; kc < 2; kc++) {
            const uint32_t kb = kc * 32;
            uint32_t a[4][4];
            #pragma unroll
            for (int mf = 0; mf < 4; mf++) ldsm4(a[mf], Hb + mf * 16 * PITCH + kb);
            uint32_t b[2][4];
            #pragma unroll
            for (int g = 0; g < 2; g++) ldsm4(b[g], Db + g * 16 * PITCH + kb);
            #pragma unroll
            for (int mf = 0; mf < 4; mf++)
                #pragma unroll
                for (int g = 0; g < 2; g++) {
                    mma16(acc[mf][g * 2 + 0], a[mf], b[g][0], b[g][2]);
                    mma16(acc[mf][g * 2 + 1], a[mf], b[g][1], b[g][3]);
                }
        }
    };

    const int KT = I_DIM / 32;   // 24 (even)
    ldgH(0, 0); CP_COMMIT();
    ldgW(0);

    for (int kt = 0; kt < KT; kt += 2) {
        // ---- body 0 (buf 0) ----
        stsW(0);
        CP_WAIT0();
        __syncthreads();
        ldgH(kt + 1, 1); CP_COMMIT();
        ldgW(kt + 1);
        compute(0);
        // ---- body 1 (buf 1) ----
        stsW(1);
        CP_WAIT0();
        __syncthreads();
        if (kt + 2 < KT) {
            ldgH(kt + 2, 0); CP_COMMIT();
            ldgW(kt + 2);
        }
        compute(1);
    }

    // epilogue: atomic accumulate into out
    #pragma unroll
    for (int mf = 0; mf < 4; mf++) {
        #pragma unroll
        for (int half = 0; half < 2; half++) {
            int rl = mw0 + mf * 16 + gid + half * 8;
            int pkk = toks[rl];
            if (pkk < 0) continue;
            float* orow = out + (size_t)(pkk >> 3) * H_DIM;
            #pragma unroll
            for (int nf = 0; nf < 4; nf++) {
                int c = col0 + nw0 + nf * 8 + 2 * tcol;
                atomicAdd(&orow[c],     acc[mf][nf][half * 2 + 0]);
                atomicAdd(&orow[c + 1], acc[mf][nf][half * 2 + 1]);
            }
        }
    }
}

// ---------------------------------------------------------------------------
extern "C" void kernel_launch(void* const* d_in, const int* in_sizes, int n_in,
                              void* d_out, int out_size)
{
    const float* x  = (const float*)d_in[0];
    const float* gw = (const float*)d_in[1];
    const float* wg = (const float*)d_in[2];
    const float* wu = (const float*)d_in[3];
    const float* wd = (const float*)d_in[4];
    float* out = (float*)d_out;

    const int smemAB = 2 * 20480;   // 40960 B
    static bool attr_done = false;
    if (!attr_done) {
        cudaFuncSetAttribute(phaseA_kernel, cudaFuncAttributeMaxDynamicSharedMemorySize, smemAB);
        cudaFuncSetAttribute(phaseB_kernel, cudaFuncAttributeMaxDynamicSharedMemorySize, smemAB);
        attr_done = true;
    }

    init_kernel<<<1024, 256>>>(out, out_size);
    router_kernel<<<T_TOK, 256>>>(x, gw);
    phaseA_kernel<<<dim3(16, I_DIM / 64, N_EXP), 256, smemAB>>>(wg, wu);
    phaseB_kernel<<<dim3(16, H_DIM / 128, N_EXP), 256, smemAB>>>(wd, out);
}